// round 1
// baseline (speedup 1.0000x reference)
#include <cuda_runtime.h>

// Problem constants (fixed shapes from reference)
#define C_DIM  256      // embed dim (K)
#define HW     4096     // H*W pixels per batch
#define BATCH  4
#define P_TOT  16384    // B * HW total pixels
#define N_SAMP 2048     // past samples
#define NPC    512      // samples per class
#define NCLS   4
#define TM     128      // pixel tile
#define TN     64       // sample tile
#define TK     16       // K chunk

// Scratch (no allocations allowed -> __device__ globals)
__device__ float g_Pn[N_SAMP * C_DIM];   // normalized past samples [n][k]
__device__ float g_inv[P_TOT];           // 1 / max(||x_p||, eps)
__device__ int   g_cls[P_TOT];           // pixel class
__device__ int   g_pcls[N_SAMP];         // past-sample class
__device__ float g_s[P_TOT * NCLS];      // per-pixel per-class exp sums

// Fast e^z for z in [-32, ~0.1], rel err < 1e-3. FMA-pipe only (no MUFU).
__device__ __forceinline__ float fexp(float z) {
    float t  = z * 1.44269504f;                 // log2(e)
    float r  = t + 12582912.0f;                 // round-to-nearest-int via 1.5*2^23
    int   i  = __float_as_int(r) - 0x4B400000;  // round(t) as int
    float fi = r - 12582912.0f;
    float f  = t - fi;                          // in [-0.5, 0.5]
    // 2^f Taylor deg-3 (rel err ~6e-4 at |f|=0.5)
    float p = fmaf(f, 0.0555041f, 0.2402265f);
    p = fmaf(f, p, 0.6931472f);
    p = fmaf(f, p, 1.0f);
    float scale = __int_as_float((i + 127) << 23);
    return p * scale;
}

__global__ void zero_kernel(float* out) {
    int i = blockIdx.x * blockDim.x + threadIdx.x;
    if (i < P_TOT * NCLS) g_s[i] = 0.0f;
    if (i == 0) *out = 0.0f;
}

// Normalize past samples; extract per-sample class from one-hot labels.
__global__ void pnorm_kernel(const float* __restrict__ P, const float* __restrict__ L) {
    int n = blockIdx.x;
    int t = threadIdx.x;          // 256 threads = C_DIM
    float v = P[n * C_DIM + t];
    __shared__ float sh[256];
    sh[t] = v * v;
    __syncthreads();
    for (int s = 128; s > 0; s >>= 1) {
        if (t < s) sh[t] += sh[t + s];
        __syncthreads();
    }
    float inv = 1.0f / fmaxf(sqrtf(sh[0]), 1e-8f);
    g_Pn[n * C_DIM + t] = v * inv;
    if (t == 0) {
        int c = 0; float best = -1.0f;
        #pragma unroll
        for (int k = 0; k < NCLS; k++) {
            float lv = L[n * NCLS + k];
            if (lv > best) { best = lv; c = k; }
        }
        g_pcls[n] = c;
    }
}

// Per-pixel inverse norm + class from one-hot y. Coalesced over v.
__global__ void xprep_kernel(const float* __restrict__ X, const float* __restrict__ Y) {
    int p = blockIdx.x * blockDim.x + threadIdx.x;
    if (p >= P_TOT) return;
    int b = p >> 12, v = p & 4095;
    const float* xb = X + (size_t)b * C_DIM * HW + v;
    float s = 0.0f;
    #pragma unroll 8
    for (int c = 0; c < C_DIM; c++) {
        float x = xb[(size_t)c * HW];
        s = fmaf(x, x, s);
    }
    g_inv[p] = 1.0f / fmaxf(sqrtf(s), 1e-8f);
    const float* yb = Y + (size_t)b * NCLS * HW + v;
    int cls = 0; float best = -1.0f;
    #pragma unroll
    for (int k = 0; k < NCLS; k++) {
        float yv = yb[(size_t)k * HW];
        if (yv > best) { best = yv; cls = k; }
    }
    g_cls[p] = cls;
}

// Fused GEMM (dot(x_p, Pn_n)) + exp epilogue + per-class reduction.
// Block tile: TM=128 pixels x TN=64 samples (one class per tile). K chunked by 16.
__global__ __launch_bounds__(256) void gemm_kernel(const float* __restrict__ X) {
    __shared__ float Xs[TK][TM];        // [kk][m]
    __shared__ float Ps[TN][TK + 1];    // padded to kill bank conflicts

    int m0 = blockIdx.x * TM;
    int n0 = blockIdx.y * TN;
    int b  = m0 >> 12;
    int v0 = m0 & 4095;
    const float* Xb = X + (size_t)b * C_DIM * HW + v0;   // [k][m] at Xb[k*HW + m]

    int t  = threadIdx.x;
    int tx = t & 15;          // pixel group: pixels tx*8 .. tx*8+7
    int ty = t >> 4;          // sample group: samples ty*4 .. ty*4+3

    float acc[4][8];
    #pragma unroll
    for (int i = 0; i < 4; i++)
        #pragma unroll
        for (int j = 0; j < 8; j++) acc[i][j] = 0.0f;

    for (int k0 = 0; k0 < C_DIM; k0 += TK) {
        // Load Xs: 16x128 floats = 512 float4, 2 per thread, coalesced
        #pragma unroll
        for (int i = 0; i < 2; i++) {
            int q  = t + i * 256;
            int kk = q >> 5;
            int mq = (q & 31) << 2;
            float4 val = *(const float4*)(Xb + (size_t)(k0 + kk) * HW + mq);
            *(float4*)&Xs[kk][mq] = val;
        }
        // Load Ps: 64x16 floats = 256 float4, 1 per thread
        {
            int n  = t >> 2;
            int kq = (t & 3) << 2;
            float4 val = *(const float4*)(&g_Pn[(size_t)(n0 + n) * C_DIM + k0 + kq]);
            Ps[n][kq + 0] = val.x; Ps[n][kq + 1] = val.y;
            Ps[n][kq + 2] = val.z; Ps[n][kq + 3] = val.w;
        }
        __syncthreads();

        #pragma unroll
        for (int kk = 0; kk < TK; kk++) {
            float4 x0 = *(const float4*)&Xs[kk][tx * 8];
            float4 x1 = *(const float4*)&Xs[kk][tx * 8 + 4];
            float xr[8] = {x0.x, x0.y, x0.z, x0.w, x1.x, x1.y, x1.z, x1.w};
            #pragma unroll
            for (int i = 0; i < 4; i++) {
                float pv = Ps[ty * 4 + i][kk];
                #pragma unroll
                for (int j = 0; j < 8; j++)
                    acc[i][j] = fmaf(pv, xr[j], acc[i][j]);
            }
        }
        __syncthreads();
    }

    // Epilogue: w = exp((sim-1)/T) = exp(10*sim - 10); sum over this tile's 64 samples
    int cls = g_pcls[n0];   // uniform across the TN=64 tile (512-aligned class blocks)
    float invn[8];
    #pragma unroll
    for (int j = 0; j < 8; j++) invn[j] = g_inv[m0 + tx * 8 + j];

    float loc[8];
    #pragma unroll
    for (int j = 0; j < 8; j++) {
        float s = 0.0f;
        #pragma unroll
        for (int i = 0; i < 4; i++) {
            float sim = acc[i][j] * invn[j];
            s += fexp(fmaf(10.0f, sim, -10.0f));
        }
        loc[j] = s;
    }

    // Reduce across the 16 ty-groups; reuse Xs (16*128 floats). Safe: synced above.
    float* red = &Xs[0][0];
    #pragma unroll
    for (int j = 0; j < 8; j++) red[ty * TM + tx * 8 + j] = loc[j];
    __syncthreads();
    if (t < TM) {
        float s = 0.0f;
        #pragma unroll
        for (int r = 0; r < 16; r++) s += red[r * TM + t];
        atomicAdd(&g_s[(size_t)(m0 + t) * NCLS + cls], s);
    }
}

__global__ void final_kernel(float* out) {
    int p = blockIdx.x * blockDim.x + threadIdx.x;
    float r = 0.0f;
    if (p < P_TOT) {
        int c = g_cls[p];
        float s0 = g_s[p * 4 + 0], s1 = g_s[p * 4 + 1];
        float s2 = g_s[p * 4 + 2], s3 = g_s[p * 4 + 3];
        float tot = s0 + s1 + s2 + s3;
        float sc  = (c == 0) ? s0 : (c == 1) ? s1 : (c == 2) ? s2 : s3;
        float sum_same  = sc + (float)(N_SAMP - NPC);
        float sum_other = (tot - sc) + (float)NPC;
        r = sum_same / sum_other;
    }
    __shared__ float sh[256];
    sh[threadIdx.x] = r;
    __syncthreads();
    for (int s = 128; s > 0; s >>= 1) {
        if (threadIdx.x < s) sh[threadIdx.x] += sh[threadIdx.x + s];
        __syncthreads();
    }
    if (threadIdx.x == 0) atomicAdd(out, sh[0] * (1.0f / (float)P_TOT));
}

extern "C" void kernel_launch(void* const* d_in, const int* in_sizes, int n_in,
                              void* d_out, int out_size) {
    const float* X = (const float*)d_in[0];   // (4,256,64,64)
    const float* Y = (const float*)d_in[1];   // (4,4,64,64)
    const float* P = (const float*)d_in[2];   // (2048,256)
    const float* L = (const float*)d_in[3];   // (2048,4)
    float* out = (float*)d_out;

    zero_kernel<<<(P_TOT * NCLS + 255) / 256, 256>>>(out);
    pnorm_kernel<<<N_SAMP, 256>>>(P, L);
    xprep_kernel<<<P_TOT / 256, 256>>>(X, Y);
    dim3 grid(P_TOT / TM, N_SAMP / TN);
    gemm_kernel<<<grid, 256>>>(X);
    final_kernel<<<P_TOT / 256, 256>>>(out);
}

// round 5
// speedup vs baseline: 6.2446x; 6.2446x over previous
#include <cuda_runtime.h>
#include <cuda_bf16.h>
#include <cstdint>

#define C_DIM  256      // K
#define HW     4096
#define P_TOT  16384    // M total
#define N_SAMP 2048     // N total
#define NPC    512
#define NCLS   4
#define TMG    64       // M tile per CTA (A tile 64x256 bf16 = 32KB)
#define TNB    32       // B tile per iter (32x256 bf16 = 16KB)
#define NITER  (N_SAMP / TNB)   // 64

// ---------------- scratch (__device__ globals; no allocs allowed) ----------------
__device__ __align__(16) __nv_bfloat16 g_Xbf[P_TOT * C_DIM];   // [pixel][k]
__device__ __align__(16) __nv_bfloat16 g_Pbf[N_SAMP * C_DIM];  // normalized, [n][k]
__device__ float g_inv10[P_TOT];    // 10 / max(||x||, eps)
__device__ int   g_cls[P_TOT];
__device__ int   g_pcls[N_SAMP];

// ---------------- helpers ----------------
static __device__ __forceinline__ uint32_t smem_u32(const void* p) {
    uint32_t a;
    asm("{ .reg .u64 t; cvta.to.shared.u64 t, %1; cvt.u32.u64 %0, t; }" : "=r"(a) : "l"(p));
    return a;
}
// Swizzled byte offset of 16B chunk (row, kchunk) in a [rows][256] bf16 tile
// (row stride 512B; chunk XORed with row&7 -> conflict-free ldmatrix).
static __device__ __forceinline__ uint32_t swz(int row, int kc) {
    return (uint32_t)(row * 512 + ((kc ^ (row & 7)) << 4));
}
static __device__ __forceinline__ void ldm4(uint32_t* r, uint32_t addr) {
    asm volatile("ldmatrix.sync.aligned.m8n8.x4.shared.b16 {%0,%1,%2,%3}, [%4];"
                 : "=r"(r[0]), "=r"(r[1]), "=r"(r[2]), "=r"(r[3]) : "r"(addr));
}
static __device__ __forceinline__ void mma16816(float* d, const uint32_t* a,
                                                uint32_t b0, uint32_t b1) {
    asm volatile(
        "mma.sync.aligned.m16n8k16.row.col.f32.bf16.bf16.f32 "
        "{%0,%1,%2,%3},{%4,%5,%6,%7},{%8,%9},{%0,%1,%2,%3};"
        : "+f"(d[0]), "+f"(d[1]), "+f"(d[2]), "+f"(d[3])
        : "r"(a[0]), "r"(a[1]), "r"(a[2]), "r"(a[3]), "r"(b0), "r"(b1));
}
static __device__ __forceinline__ void cpasync16(uint32_t dst, const void* src) {
    asm volatile("cp.async.cg.shared.global [%0], [%1], 16;" :: "r"(dst), "l"(src));
}
#define CP_COMMIT() asm volatile("cp.async.commit_group;" ::: "memory")
#define CP_WAIT0()  asm volatile("cp.async.wait_group 0;" ::: "memory")

// ---------------- kernels ----------------
__global__ void zero_kernel(float* out) { if (threadIdx.x == 0) *out = 0.0f; }

// Normalize past samples -> bf16; per-sample class from one-hot labels.
__global__ void pnorm_kernel(const float* __restrict__ P, const float* __restrict__ L) {
    int n = blockIdx.x;
    int t = threadIdx.x;             // = channel
    float v = P[n * C_DIM + t];
    __shared__ float sh[256];
    sh[t] = v * v;
    __syncthreads();
    for (int s = 128; s > 0; s >>= 1) { if (t < s) sh[t] += sh[t + s]; __syncthreads(); }
    float inv = 1.0f / fmaxf(sqrtf(sh[0]), 1e-8f);
    g_Pbf[n * C_DIM + t] = __float2bfloat16(v * inv);
    if (t == 0) {
        int c = 0; float best = -1.0f;
        #pragma unroll
        for (int k = 0; k < NCLS; k++) { float lv = L[n * NCLS + k]; if (lv > best) { best = lv; c = k; } }
        g_pcls[n] = c;
    }
}

// Transpose X [b][c][v] -> g_Xbf[pixel][c] bf16; norms; pixel class.
__global__ void prep_kernel(const float* __restrict__ X, const float* __restrict__ Y) {
    int p = blockIdx.x * 256 + threadIdx.x;
    int b = p >> 12, v = p & 4095;
    const float* xb = X + (size_t)b * C_DIM * HW + v;
    float nrm = 0.0f;
    for (int c0 = 0; c0 < C_DIM; c0 += 8) {
        uint4 pk;
        __nv_bfloat16* bp = (__nv_bfloat16*)&pk;
        #pragma unroll
        for (int j = 0; j < 8; j++) {
            float x = xb[(size_t)(c0 + j) * HW];
            nrm = fmaf(x, x, nrm);
            bp[j] = __float2bfloat16(x);
        }
        *(uint4*)(&g_Xbf[(size_t)p * C_DIM + c0]) = pk;
    }
    g_inv10[p] = 10.0f / fmaxf(sqrtf(nrm), 1e-8f);
    const float* yb = Y + (size_t)b * NCLS * HW + v;
    int cls = 0; float best = -1.0f;
    #pragma unroll
    for (int k = 0; k < NCLS; k++) { float yv = yb[(size_t)k * HW]; if (yv > best) { best = yv; cls = k; } }
    g_cls[p] = cls;
}

// bf16 mma.sync GEMM + exp epilogue + per-pixel ratio.
// One CTA per 64 pixels; 4 warps in 2(M)x2(N); warp tile 32(M)x16(N).
// Static smem only (48KB) -> no cudaFuncSetAttribute needed.
__global__ __launch_bounds__(128) void gemm_kernel(float* __restrict__ out) {
    __shared__ __align__(128) char sm[49152];   // A 32KB @0, B 16KB @32768
    uint32_t sA = smem_u32(sm);
    uint32_t sB = sA + 32768;
    int t = threadIdx.x, wid = t >> 5, lane = t & 31;
    int mw = wid & 1, nw = wid >> 1;
    int m0 = blockIdx.x * TMG;

    // Load A tile: 64 rows x 32 16B-chunks = 2048 chunks, 16 per thread.
    #pragma unroll
    for (int i = 0; i < 16; i++) {
        int idx = t + i * 128;
        int row = idx >> 5, kc = idx & 31;
        cpasync16(sA + swz(row, kc), g_Xbf + (size_t)(m0 + row) * C_DIM + kc * 8);
    }
    CP_COMMIT();

    // rows owned by this lane: m0 + mw*32 + (s>>1)*16 + (s&1)*8 + (lane>>2)
    float inv_r[4];
    #pragma unroll
    for (int s = 0; s < 4; s++)
        inv_r[s] = g_inv10[m0 + mw * 32 + (s >> 1) * 16 + (s & 1) * 8 + (lane >> 2)];

    float cls_acc[4][NCLS];
    #pragma unroll
    for (int s = 0; s < 4; s++)
        #pragma unroll
        for (int c = 0; c < NCLS; c++) cls_acc[s][c] = 0.0f;

    for (int it = 0; it < NITER; it++) {
        // Load B tile: 32 rows x 32 chunks = 1024 chunks, 8 per thread.
        const __nv_bfloat16* bsrc = g_Pbf + (size_t)it * TNB * C_DIM;
        #pragma unroll
        for (int i = 0; i < 8; i++) {
            int idx = t + i * 128;
            int row = idx >> 5, kc = idx & 31;
            cpasync16(sB + swz(row, kc), bsrc + (size_t)row * C_DIM + kc * 8);
        }
        CP_COMMIT();
        CP_WAIT0();
        __syncthreads();

        float d[2][2][4];
        #pragma unroll
        for (int i = 0; i < 2; i++)
            #pragma unroll
            for (int j = 0; j < 2; j++)
                #pragma unroll
                for (int q = 0; q < 4; q++) d[i][j][q] = 0.0f;

        #pragma unroll
        for (int ks = 0; ks < 16; ks++) {
            uint32_t a[2][4];
            #pragma unroll
            for (int i = 0; i < 2; i++) {
                int row = mw * 32 + i * 16 + (lane & 15);
                int kc  = ks * 2 + (lane >> 4);
                ldm4(a[i], sA + swz(row, kc));
            }
            uint32_t b[4];
            {
                int n  = nw * 16 + ((lane >> 4) << 3) + (lane & 7);
                int kc = ks * 2 + ((lane >> 3) & 1);
                ldm4(b, sB + swz(n, kc));
            }
            #pragma unroll
            for (int i = 0; i < 2; i++) {
                mma16816(d[i][0], a[i], b[0], b[1]);
                mma16816(d[i][1], a[i], b[2], b[3]);
            }
        }

        // epilogue: all 32 cols this iter share one class
        int cls = g_pcls[it * TNB];
        #pragma unroll
        for (int i = 0; i < 2; i++) {
            float sh0 = 0.0f, sh1 = 0.0f;
            #pragma unroll
            for (int j = 0; j < 2; j++) {
                sh0 += __expf(fmaf(d[i][j][0], inv_r[i * 2], -10.0f))
                     + __expf(fmaf(d[i][j][1], inv_r[i * 2], -10.0f));
                sh1 += __expf(fmaf(d[i][j][2], inv_r[i * 2 + 1], -10.0f))
                     + __expf(fmaf(d[i][j][3], inv_r[i * 2 + 1], -10.0f));
            }
            cls_acc[i * 2][cls]     += sh0;
            cls_acc[i * 2 + 1][cls] += sh1;
        }

        __syncthreads();   // everyone done reading sB before next overwrite
    }

    // ---- reduction: quad lanes + the 2 n-warps -> per (row, class) in smem ----
    float* sRed = (float*)sm;              // 64 rows x 4 classes = 256 floats
    float* red2 = (float*)(sm + 1024);     // 128 floats block reduce
    sRed[t] = 0.0f; sRed[t + 128] = 0.0f;
    __syncthreads();
    #pragma unroll
    for (int s = 0; s < 4; s++) {
        int row = mw * 32 + (s >> 1) * 16 + (s & 1) * 8 + (lane >> 2);
        #pragma unroll
        for (int c = 0; c < NCLS; c++) {
            float v = cls_acc[s][c];
            v += __shfl_xor_sync(0xFFFFFFFFu, v, 1);
            v += __shfl_xor_sync(0xFFFFFFFFu, v, 2);
            if ((lane & 3) == 0) atomicAdd(&sRed[row * NCLS + c], v);
        }
    }
    __syncthreads();

    float rr = 0.0f;
    if (t < TMG) {
        int p = m0 + t;
        int cl = g_cls[p];
        float v0 = sRed[t * 4], v1 = sRed[t * 4 + 1], v2 = sRed[t * 4 + 2], v3 = sRed[t * 4 + 3];
        float tot = v0 + v1 + v2 + v3;
        float sc = (cl == 0) ? v0 : (cl == 1) ? v1 : (cl == 2) ? v2 : v3;
        rr = (sc + (float)(N_SAMP - NPC)) / ((tot - sc) + (float)NPC);
    }
    red2[t] = rr;
    __syncthreads();
    for (int s = 64; s > 0; s >>= 1) { if (t < s) red2[t] += red2[t + s]; __syncthreads(); }
    if (t == 0) atomicAdd(out, red2[0] * (1.0f / (float)P_TOT));
}

extern "C" void kernel_launch(void* const* d_in, const int* in_sizes, int n_in,
                              void* d_out, int out_size) {
    const float* X = (const float*)d_in[0];   // (4,256,64,64)
    const float* Y = (const float*)d_in[1];   // (4,4,64,64)
    const float* P = (const float*)d_in[2];   // (2048,256)
    const float* L = (const float*)d_in[3];   // (2048,4)
    float* out = (float*)d_out;

    zero_kernel<<<1, 32>>>(out);
    pnorm_kernel<<<N_SAMP, 256>>>(P, L);
    prep_kernel<<<P_TOT / 256, 256>>>(X, Y);
    gemm_kernel<<<P_TOT / TMG, 128>>>(out);
}